// round 9
// baseline (speedup 1.0000x reference)
#include <cuda_runtime.h>
#include <cuda_bf16.h>

// Dual marching cubes, GRID=192, ISO=0.
// R9: split-role blocks in ONE launch.
//  - cell blocks: corner loads, vertex mean, vmask, qmask (signs reused)
//  - quad blocks: pure-index quad emission, 2 quads per thread via st.global.v8.f32
// Output (float32, concatenated, reference order):
//   verts  [193^3 * 3]       at V_OFF  = 0
//   vmask  [193^3]           at VM_OFF = 21,567,171
//   quads  [3*193*192*192*4] at Q_OFF  = 28,756,228
//   qmask  [3*193*192*192]   at QM_OFF = 114,133,252

#define GD   192
#define C    193
#define C2   (C*C)          // 37249
#define NC   (C*C*C)        // 7,189,057
#define NEX  (C*GD*GD)      // 7,114,752
#define NQ   (3*NEX)        // 21,344,256
#define V_OFF  0
#define VM_OFF (3*NC)
#define Q_OFF  (VM_OFF + NC)
#define QM_OFF (Q_OFF + 4*NQ)

#define NCB  146            // cell blocks per slab (146*256 >= C2)
#define QXB  216            // quad-pair blocks in x: 216*193*256 = 10,672,128 pairs
#define UMAX 10672127       // last pair index: handles edge 3*NEX-1 (single) + edge 0

// quad content for edge e (flat over [x|y|z] edge spaces): f0 + constant offsets
__device__ __forceinline__ float4 quad_of(int e) {
    int f0, d1, d2, d3;
    if (e < NEX) {                      // x-edges: l = (i*192 + j)*192 + k
        int l = e;
        int i = l / 36864; int rem = l - i * 36864;
        int j = rem / 192; int k = rem - j * 192;
        f0 = 37249 * i + 193 * j + k;   // cid(i, j, k)
        d1 = 193; d2 = 194; d3 = 1;
    } else if (e < 2 * NEX) {           // y-edges: l = (i*193 + j)*192 + k
        int l = e - NEX;
        int i = l / 37056; int rem = l - i * 37056;
        int j = rem / 192; int k = rem - j * 192;
        f0 = 37249 * i + 193 * j + k;
        d1 = 37249; d2 = 37250; d3 = 1;
    } else {                            // z-edges: l = (i*192 + j)*193 + k
        int l = e - 2 * NEX;
        int i = l / 37056; int rem = l - i * 37056;
        int j = rem / 193; int k = rem - j * 193;
        f0 = 37249 * i + 193 * j + k;
        d1 = 37249; d2 = 37442; d3 = 193;
    }
    float f = (float)f0;                // < 2^23, exact
    return make_float4(f, f + (float)d1, f + (float)d2, f + (float)d3);
}

__device__ __forceinline__ void st_v8(float* p, float4 a, float4 b) {
    asm volatile("st.global.v8.f32 [%0], {%1,%2,%3,%4,%5,%6,%7,%8};"
                 :: "l"(p), "f"(a.x), "f"(a.y), "f"(a.z), "f"(a.w),
                    "f"(b.x), "f"(b.y), "f"(b.z), "f"(b.w) : "memory");
}

__global__ void __launch_bounds__(256, 8)
dmc9(const float* __restrict__ g, float* __restrict__ out)
{
    const int a = blockIdx.y;

    // ====================== quad blocks: pure index -> stores =================
    if (blockIdx.x >= NCB) {
        const int p = (blockIdx.x - NCB) * C + a;         // [0, QXB*193)
        const int u = p * 256 + threadIdx.x;              // pair index
        const int e = 2 * u + 1;                          // odd -> 32B aligned
        float* qp = out + Q_OFF + 4 * (size_t)e;
        if (u < UMAX) {
            st_v8(qp, quad_of(e), quad_of(e + 1));        // edges e, e+1
        } else if (u == UMAX) {
            // last pair is a single edge (3*NEX-1); also cover edge 0
            __stcs((float4*)qp, quad_of(e));
            __stcs((float4*)(out + Q_OFF), quad_of(0));
        }
        return;
    }

    // ====================== cell blocks: verts + vmask + qmask ================
    const int r = blockIdx.x * 256 + threadIdx.x;
    if (r >= C2) return;
    const int b = r / C;
    const int c = r - b * C;
    const int cidx = a * C2 + r;

    // corner k: dx=k&1 (a), dy=(k>>1)&1 (b), dz=(k>>2)&1 (c); P[a+dx, b+dy, c+dz]
    float v[8];
    const int ga = a - 1, gb = b - 1, gc = c - 1;
    const bool interior = (a >= 1) & (a <= GD - 1) & (b >= 1) & (b <= GD - 1) & (c >= 1) & (c <= GD - 1);
    if (interior) {
        const float* p = g + ((ga * GD + gb) * GD + gc);
        #pragma unroll
        for (int k = 0; k < 8; k++) {
            int dx = k & 1, dy = (k >> 1) & 1, dz = (k >> 2) & 1;
            v[k] = __ldg(p + (dx * GD + dy) * GD + dz);
        }
    } else {
        #pragma unroll
        for (int k = 0; k < 8; k++) {
            int x = ga + (k & 1), y = gb + ((k >> 1) & 1), z = gc + ((k >> 2) & 1);
            bool in = ((unsigned)x < (unsigned)GD) & ((unsigned)y < (unsigned)GD) & ((unsigned)z < (unsigned)GD);
            v[k] = in ? __ldg(g + (x * GD + y) * GD + z) : 1.0f;   // pad = iso+1
        }
    }

    // qmask (4 corner signs), same offsets as before:
    //   o0 = 36864*a + r - b - 193 ; o1 = 37056*(a-1) + r - b - 1 ; o2 = 37056*(a-1) + r - 193
    {
        const bool s0 = v[0] < 0.f, s1 = v[1] < 0.f, s2v = v[2] < 0.f, s4v = v[4] < 0.f;
        const int t1 = 37056 * a - 37056 + r;
        if ((b >= 1) & (c >= 1))
            __stcs(out + QM_OFF + (36864 * a + r - b - 193), (s0 != s1) ? 1.f : 0.f);
        if ((a >= 1) & (c >= 1))
            __stcs(out + QM_OFF + NEX + (t1 - b - 1), (s0 != s2v) ? 1.f : 0.f);
        if ((a >= 1) & (b >= 1))
            __stcs(out + QM_OFF + 2 * NEX + (t1 - 193), (s0 != s4v) ? 1.f : 0.f);
    }

    // vertex: 12-edge crossing mean
    const int EA[12] = {0,2,4,6, 0,1,4,5, 0,1,2,3};
    float sx = 0.f, sy = 0.f, sz = 0.f, cnt = 0.f;
    #pragma unroll
    for (int e = 0; e < 12; e++) {
        int axis = e >> 2;
        int A = EA[e];
        int B = A + (1 << axis);
        float vA = v[A], vB = v[B];
        bool m = (vA < 0.f) != (vB < 0.f);
        if (m) {
            float tt = __fdividef(vA, vA - vB);   // == (0 - vA)/(vB - vA)
            float px = (axis == 0) ? tt : (float)(A & 1);
            float py = (axis == 1) ? tt : (float)((A >> 1) & 1);
            float pz = (axis == 2) ? tt : (float)((A >> 2) & 1);
            sx += px; sy += py; sz += pz; cnt += 1.f;
        }
    }

    const float inv = __fdividef(1.f, fmaxf(cnt, 1.f));
    const float nrm = 1.0f / (float)(GD - 1);
    float fx = ((float)a + sx * inv - 1.f) * nrm;
    float fy = ((float)b + sy * inv - 1.f) * nrm;
    float fz = ((float)c + sz * inv - 1.f) * nrm;

    __stcs(out + VM_OFF + cidx, (cnt > 0.f) ? 1.f : 0.f);

    // direct stride-3 vert stores: warp covers 3 full 128B lines, all bytes written
    float* vo = out + V_OFF + 3 * cidx;
    __stcs(vo + 0, fx);
    __stcs(vo + 1, fy);
    __stcs(vo + 2, fz);
}

extern "C" void kernel_launch(void* const* d_in, const int* in_sizes, int n_in,
                              void* d_out, int out_size)
{
    const float* g = (const float*)d_in[0];
    float* out = (float*)d_out;
    dim3 grid(NCB + QXB, C, 1);
    dmc9<<<grid, 256>>>(g, out);
}

// round 10
// speedup vs baseline: 1.3884x; 1.3884x over previous
#include <cuda_runtime.h>
#include <cuda_bf16.h>

// Dual marching cubes, GRID=192, ISO=0.
// R10: R8 body exactly, but all output stores use st.global.wt (write-through)
// instead of .cs — testing whether the ~5.7 TB/s plateau is an L2 fill+drain
// artifact or the raw HBM write ceiling.
// Output (float32, concatenated, reference order):
//   verts  [193^3 * 3]       at V_OFF  = 0
//   vmask  [193^3]           at VM_OFF = 21,567,171
//   quads  [3*193*192*192*4] at Q_OFF  = 28,756,228
//   qmask  [3*193*192*192]   at QM_OFF = 114,133,252

#define GD   192
#define C    193
#define C2   (C*C)          // 37249
#define NC   (C*C*C)        // 7,189,057
#define NEX  (C*GD*GD)      // 7,114,752
#define NQ   (3*NEX)
#define V_OFF  0
#define VM_OFF (3*NC)
#define Q_OFF  (VM_OFF + NC)
#define QM_OFF (Q_OFF + 4*NQ)

#define BX 146              // 146*256 = 37376 >= C2

__device__ __forceinline__ void stwt1(float* p, float v) {
    asm volatile("st.global.wt.f32 [%0], %1;" :: "l"(p), "f"(v) : "memory");
}
__device__ __forceinline__ void stwt4(float4* p, float4 v) {
    asm volatile("st.global.wt.v4.f32 [%0], {%1,%2,%3,%4};"
                 :: "l"(p), "f"(v.x), "f"(v.y), "f"(v.z), "f"(v.w) : "memory");
}

__global__ void __launch_bounds__(256, 8)
dmc10(const float* __restrict__ g, float* __restrict__ out)
{
    const int a = blockIdx.y;                  // slab (uniform per block)
    const int r = blockIdx.x * 256 + threadIdx.x;
    if (r >= C2) return;                       // no smem/barrier -> legal
    const int b = r / C;
    const int c = r - b * C;
    const int cidx = a * C2 + r;

    // quad output flat offsets:
    //   o0 = (a*192 + b-1)*192 + (c-1) = 36864*a + r - b - 193
    //   o1 = ((a-1)*193 + b)*192 + c-1 = 37056*a - 37056 + r - b - 1
    //   o2 = ((a-1)*192 + b-1)*193 + c = 37056*a - 37056 + r - 193
    const int t1 = 37056 * a - 37056 + r;
    const int o0 = 36864 * a + r - b - 193;
    const int o1 = t1 - b - 1;
    const int o2 = t1 - 193;
    const bool q0 = (b >= 1) & (c >= 1);
    const bool q1 = (a >= 1) & (c >= 1);
    const bool q2 = (a >= 1) & (b >= 1);

    // ---------------- quads first: pure function of index, store early ----------------
    {
        const float fb = (float)cidx;
        float4* qb = (float4*)(out + Q_OFF);
        if (q0) stwt4(qb + o0,           make_float4(fb - 194.f,   fb - 1.f,   fb, fb - 193.f));
        if (q1) stwt4(qb + NEX + o1,     make_float4(fb - 37250.f, fb - 1.f,   fb, fb - 37249.f));
        if (q2) stwt4(qb + 2 * NEX + o2, make_float4(fb - 37442.f, fb - 193.f, fb, fb - 37249.f));
    }

    // ---------------- corner loads ----------------
    // corner k: dx=k&1 (a), dy=(k>>1)&1 (b), dz=(k>>2)&1 (c); P[a+dx, b+dy, c+dz]
    float v[8];
    const int ga = a - 1, gb = b - 1, gc = c - 1;
    const bool interior = (a >= 1) & (a <= GD - 1) & (b >= 1) & (b <= GD - 1) & (c >= 1) & (c <= GD - 1);
    if (interior) {
        const float* p = g + ((ga * GD + gb) * GD + gc);
        #pragma unroll
        for (int k = 0; k < 8; k++) {
            int dx = k & 1, dy = (k >> 1) & 1, dz = (k >> 2) & 1;
            v[k] = __ldg(p + (dx * GD + dy) * GD + dz);
        }
    } else {
        #pragma unroll
        for (int k = 0; k < 8; k++) {
            int x = ga + (k & 1), y = gb + ((k >> 1) & 1), z = gc + ((k >> 2) & 1);
            bool in = ((unsigned)x < (unsigned)GD) & ((unsigned)y < (unsigned)GD) & ((unsigned)z < (unsigned)GD);
            v[k] = in ? __ldg(g + (x * GD + y) * GD + z) : 1.0f;   // pad = iso+1
        }
    }

    // ---------------- qmask (needs only 4 corner signs) ----------------
    {
        const bool s0 = v[0] < 0.f, s1 = v[1] < 0.f, s2v = v[2] < 0.f, s4v = v[4] < 0.f;
        if (q0) stwt1(out + QM_OFF + o0,           (s0 != s1)  ? 1.f : 0.f);
        if (q1) stwt1(out + QM_OFF + NEX + o1,     (s0 != s2v) ? 1.f : 0.f);
        if (q2) stwt1(out + QM_OFF + 2 * NEX + o2, (s0 != s4v) ? 1.f : 0.f);
    }

    // ---------------- vertex: 12-edge crossing mean ----------------
    const int EA[12] = {0,2,4,6, 0,1,4,5, 0,1,2,3};
    float sx = 0.f, sy = 0.f, sz = 0.f, cnt = 0.f;
    #pragma unroll
    for (int e = 0; e < 12; e++) {
        int axis = e >> 2;
        int A = EA[e];
        int B = A + (1 << axis);
        float vA = v[A], vB = v[B];
        bool m = (vA < 0.f) != (vB < 0.f);
        if (m) {
            float tt = __fdividef(vA, vA - vB);   // == (0 - vA)/(vB - vA)
            float px = (axis == 0) ? tt : (float)(A & 1);
            float py = (axis == 1) ? tt : (float)((A >> 1) & 1);
            float pz = (axis == 2) ? tt : (float)((A >> 2) & 1);
            sx += px; sy += py; sz += pz; cnt += 1.f;
        }
    }

    const float inv = __fdividef(1.f, fmaxf(cnt, 1.f));
    const float nrm = 1.0f / (float)(GD - 1);
    float fx = ((float)a + sx * inv - 1.f) * nrm;
    float fy = ((float)b + sy * inv - 1.f) * nrm;
    float fz = ((float)c + sz * inv - 1.f) * nrm;

    stwt1(out + VM_OFF + cidx, (cnt > 0.f) ? 1.f : 0.f);

    // direct stride-3 vert stores: warp covers 3 full 128B lines, all bytes written
    float* vo = out + V_OFF + 3 * cidx;
    stwt1(vo + 0, fx);
    stwt1(vo + 1, fy);
    stwt1(vo + 2, fz);
}

extern "C" void kernel_launch(void* const* d_in, const int* in_sizes, int n_in,
                              void* d_out, int out_size)
{
    const float* g = (const float*)d_in[0];
    float* out = (float*)d_out;
    dim3 grid(BX, C, 1);
    dmc10<<<grid, 256>>>(g, out);
}

// round 11
// speedup vs baseline: 1.4391x; 1.0365x over previous
#include <cuda_runtime.h>
#include <cuda_bf16.h>

// Dual marching cubes, GRID=192, ISO=0.
// R11: consolidated floor kernel. R4 structure (1D grid over cells, smem vert
// staging, __stcs, 32 regs / 96% occ) + R8 constant-folded quad offsets +
// early quad stores. The kernel is at the LTS byte ceiling (~5.7 TB/s writes
// = ~11.3 TB/s L2-array traffic): output bytes are mandated, so this is the floor.
// Output (float32, concatenated, reference order):
//   verts  [193^3 * 3]       at V_OFF  = 0
//   vmask  [193^3]           at VM_OFF = 21,567,171
//   quads  [3*193*192*192*4] at Q_OFF  = 28,756,228
//   qmask  [3*193*192*192]   at QM_OFF = 114,133,252

#define GD   192
#define C    193
#define C2   (C*C)          // 37249
#define NC   (C*C*C)        // 7,189,057
#define NEX  (C*GD*GD)      // 7,114,752
#define NQ   (3*NEX)
#define V_OFF  0
#define VM_OFF (3*NC)
#define Q_OFF  (VM_OFF + NC)
#define QM_OFF (Q_OFF + 4*NQ)
#define NVB ((NC + 255) / 256)    // 28083 blocks

__global__ void __launch_bounds__(256, 8)
dmc11(const float* __restrict__ g, float* __restrict__ out)
{
    __shared__ float s[768];
    const int tid  = threadIdx.x;
    const int base = blockIdx.x * 256;
    const int idx  = base + tid;
    const bool active = idx < NC;
    const int cidx = active ? idx : (NC - 1);

    // cidx = (a*C + b)*C + c
    const int c  = cidx % C;
    const int t2 = cidx / C;
    const int b  = t2 % C;
    const int a  = t2 / C;

    // quad output flat offsets (r = b*C + c = cidx - a*C2):
    //   o0 = 36864*a + r - b - 193
    //   o1 = 37056*(a-1) + r - b - 1
    //   o2 = 37056*(a-1) + r - 193
    const int r  = cidx - a * C2;
    const int t1 = 37056 * a - 37056 + r;
    const int o0 = 36864 * a + r - b - 193;
    const int o1 = t1 - b - 1;
    const int o2 = t1 - 193;
    const bool q0 = active & (b >= 1) & (c >= 1);
    const bool q1 = active & (a >= 1) & (c >= 1);
    const bool q2 = active & (a >= 1) & (b >= 1);

    // ---------------- quads first: pure function of index, store early ----------------
    {
        const float fb = (float)cidx;
        float4* qb = (float4*)(out + Q_OFF);
        if (q0) __stcs(qb + o0,           make_float4(fb - 194.f,   fb - 1.f,   fb, fb - 193.f));
        if (q1) __stcs(qb + NEX + o1,     make_float4(fb - 37250.f, fb - 1.f,   fb, fb - 37249.f));
        if (q2) __stcs(qb + 2 * NEX + o2, make_float4(fb - 37442.f, fb - 193.f, fb, fb - 37249.f));
    }

    // ---------------- corner loads ----------------
    // corner k: dx=k&1 (a), dy=(k>>1)&1 (b), dz=(k>>2)&1 (c); P[a+dx, b+dy, c+dz]
    float v[8];
    const int ga = a - 1, gb = b - 1, gc = c - 1;
    const bool interior = (a >= 1) & (a <= GD - 1) & (b >= 1) & (b <= GD - 1) & (c >= 1) & (c <= GD - 1);
    if (interior) {
        const float* p = g + ((ga * GD + gb) * GD + gc);
        #pragma unroll
        for (int k = 0; k < 8; k++) {
            int dx = k & 1, dy = (k >> 1) & 1, dz = (k >> 2) & 1;
            v[k] = __ldg(p + (dx * GD + dy) * GD + dz);
        }
    } else {
        #pragma unroll
        for (int k = 0; k < 8; k++) {
            int x = ga + (k & 1), y = gb + ((k >> 1) & 1), z = gc + ((k >> 2) & 1);
            bool in = ((unsigned)x < (unsigned)GD) & ((unsigned)y < (unsigned)GD) & ((unsigned)z < (unsigned)GD);
            v[k] = in ? __ldg(g + (x * GD + y) * GD + z) : 1.0f;   // pad = iso+1
        }
    }

    // ---------------- qmask (needs only 4 corner signs) ----------------
    {
        const bool s0 = v[0] < 0.f, s1 = v[1] < 0.f, s2v = v[2] < 0.f, s4v = v[4] < 0.f;
        if (q0) __stcs(out + QM_OFF + o0,           (s0 != s1)  ? 1.f : 0.f);
        if (q1) __stcs(out + QM_OFF + NEX + o1,     (s0 != s2v) ? 1.f : 0.f);
        if (q2) __stcs(out + QM_OFF + 2 * NEX + o2, (s0 != s4v) ? 1.f : 0.f);
    }

    // ---------------- vertex: 12-edge crossing mean ----------------
    const int EA[12] = {0,2,4,6, 0,1,4,5, 0,1,2,3};
    float sx = 0.f, sy = 0.f, sz = 0.f, cnt = 0.f;
    #pragma unroll
    for (int e = 0; e < 12; e++) {
        int axis = e >> 2;
        int A = EA[e];
        int B = A + (1 << axis);
        float vA = v[A], vB = v[B];
        bool m = (vA < 0.f) != (vB < 0.f);
        if (m) {
            float tt = __fdividef(vA, vA - vB);   // == (0 - vA)/(vB - vA)
            float px = (axis == 0) ? tt : (float)(A & 1);
            float py = (axis == 1) ? tt : (float)((A >> 1) & 1);
            float pz = (axis == 2) ? tt : (float)((A >> 2) & 1);
            sx += px; sy += py; sz += pz; cnt += 1.f;
        }
    }

    const float inv = __fdividef(1.f, fmaxf(cnt, 1.f));
    const float nrm = 1.0f / (float)(GD - 1);
    float fx = ((float)a + sx * inv - 1.f) * nrm;
    float fy = ((float)b + sy * inv - 1.f) * nrm;
    float fz = ((float)c + sz * inv - 1.f) * nrm;

    if (active) __stcs(out + VM_OFF + idx, (cnt > 0.f) ? 1.f : 0.f);

    // ---------------- vert stores: stage stride-3 via smem -> coalesced ----------------
    s[tid * 3 + 0] = fx;
    s[tid * 3 + 1] = fy;
    s[tid * 3 + 2] = fz;
    __syncthreads();
    const int outb = base * 3;
    #pragma unroll
    for (int i = 0; i < 3; i++) {
        int o = outb + tid + i * 256;
        if (o < 3 * NC) __stcs(out + V_OFF + o, s[tid + i * 256]);
    }
}

extern "C" void kernel_launch(void* const* d_in, const int* in_sizes, int n_in,
                              void* d_out, int out_size)
{
    const float* g = (const float*)d_in[0];
    float* out = (float*)d_out;
    dmc11<<<NVB, 256>>>(g, out);
}